// round 10
// baseline (speedup 1.0000x reference)
#include <cuda_runtime.h>
#include <cstdint>

// KV-cache concat: out = [keys | values]
//   keys   = concat(key_cache[B,H,S,D],   key_states[B,H,1,D],   dim=-2)
//   values = concat(value_cache[B,H,S,D], value_states[B,H,1,D], dim=-2)
// B=8, H=32, S=4096, D=128, f32. Pure HBM-bound streaming copy.
//
// FINAL (== R8, best measured: 305.66us wall, kernel 299.4us @ 88.2% DRAM,
// 7.0 TB/s). Full config space mapped over R1-R9:
//  - single fused kernel (separate state launch: +5.8us serialized)
//  - branch-free bulk mapping: S*D4 = 2^17 -> out = j + (j>>17)*32
//  - UNROLL=8 front-batched float4 loads, u-stride = TPB strided window
//    (beats UNROLL=4/16 and per-warp-contiguous windows)
//  - TPB=512 (beats 256 by ~0.5us scheduling overhead; 1024 ties w/ worse
//    kernel time)
//  - __ldcs/__stcs streaming hints (read-once/write-once)
//  - exact grid, no guards; state rows fused into first blocks per tensor
// DRAM pinned at the top of B300's 88-92% bidirectional-stream uniformity
// band; issue 2.7%, all compute pipes idle; 2.15 GB traffic irreducible.

static constexpr int B = 8;
static constexpr int H = 32;
static constexpr int S = 4096;
static constexpr int D = 128;
static constexpr int D4 = D / 4;                        // 32 float4 per row
static constexpr int SLAB4 = (S + 1) * D4;              // 131104 float4 per (b,h)
static constexpr long long CACHE4 = (long long)B * H * S * D4;   // 2^25
static constexpr long long TENSOR4 = (long long)B * H * SLAB4;   // float4 per out tensor

static constexpr int TPB = 512;
static constexpr int UNROLL = 8;
static constexpr int BLOCKS_PER_TENSOR = (int)(CACHE4 / (TPB * UNROLL));  // 8192 exact
static constexpr int STATE_BLOCKS = (B * H * D4) / TPB; // 16

__global__ __launch_bounds__(TPB)
void kv_concat_fused_kernel(const float4* __restrict__ key_cache,
                            const float4* __restrict__ value_cache,
                            const float4* __restrict__ key_states,
                            const float4* __restrict__ value_states,
                            float4* __restrict__ out)
{
    const int t = blockIdx.y;                       // 0 = keys, 1 = values
    const float4* __restrict__ src = t ? value_cache : key_cache;
    float4* __restrict__ dst = out + (long long)t * TENSOR4;

    const long long j0 = (long long)blockIdx.x * (TPB * UNROLL) + threadIdx.x;

    // Front-batched loads (MLP = 8), streaming (evict-first) reads.
    float4 v[UNROLL];
#pragma unroll
    for (int u = 0; u < UNROLL; u++)
        v[u] = __ldcs(src + (j0 + (long long)u * TPB));

    // Streaming stores. out index = j + (bh<<5), bh = j>>17 (S*D4 = 2^17).
#pragma unroll
    for (int u = 0; u < UNROLL; u++) {
        long long j = j0 + (long long)u * TPB;
        __stcs(dst + (j + ((j >> 17) << 5)), v[u]);
    }

    // Fused state append: first STATE_BLOCKS blocks of each tensor write the
    // single new row per (b,h). One extra float4 per thread here (2 MB total).
    if (blockIdx.x < STATE_BLOCKS) {
        const int i = blockIdx.x * TPB + threadIdx.x;   // 0..8191
        const int bh   = i >> 5;                        // 0..255
        const int lane = i & 31;                        // 0..31
        const float4* __restrict__ states = t ? value_states : key_states;
        float4 sv = __ldcs(states + ((long long)bh * D4 + lane));
        dst[(long long)bh * SLAB4 + (long long)S * D4 + lane] = sv;
    }
}

extern "C" void kernel_launch(void* const* d_in, const int* in_sizes, int n_in,
                              void* d_out, int out_size)
{
    const float4* key_cache    = (const float4*)d_in[0];
    const float4* value_cache  = (const float4*)d_in[1];
    const float4* key_states   = (const float4*)d_in[2];
    const float4* value_states = (const float4*)d_in[3];
    float4* out = (float4*)d_out;

    dim3 grid(BLOCKS_PER_TENSOR, 2, 1);             // (8192, 2)
    kv_concat_fused_kernel<<<grid, TPB>>>(key_cache, value_cache,
                                          key_states, value_states, out);
}

// round 11
// speedup vs baseline: 1.0026x; 1.0026x over previous
#include <cuda_runtime.h>
#include <cstdint>

// KV-cache concat: out = [keys | values]
//   keys   = concat(key_cache[B,H,S,D],   key_states[B,H,1,D],   dim=-2)
//   values = concat(value_cache[B,H,S,D], value_states[B,H,1,D], dim=-2)
// B=8, H=32, S=4096, D=128, f32. Pure HBM-bound streaming copy.
//
// FINAL (best measured config; 305.66-306.43us wall across 3 runs, kernel
// 299.4-300.0us @ 88.0-88.2% DRAM, ~7.0 TB/s). Config space fully mapped
// over R1-R10:
//  - single fused kernel (separate state launch: +5.8us serialized)
//  - branch-free bulk mapping: S*D4 = 2^17 -> out = j + (j>>17)*32
//  - UNROLL=8 front-batched float4 loads, u-stride = TPB strided window
//    (beats UNROLL=4/16 and per-warp-contiguous windows)
//  - TPB=512 (beats 256; ties 1024 with better kernel time)
//  - __ldcs/__stcs streaming hints (read-once/write-once)
//  - exact grid, no guards; state rows fused into first blocks per tensor
// DRAM pinned at the top of B300's 88-92% bidirectional-stream uniformity
// band; issue 2.7%, compute pipes idle; 2.15 GB traffic irreducible. CE /
// memcpy2D / concurrent-split alternatives share the same path-independent
// LTS/DRAM ceiling and only add overhead.

static constexpr int B = 8;
static constexpr int H = 32;
static constexpr int S = 4096;
static constexpr int D = 128;
static constexpr int D4 = D / 4;                        // 32 float4 per row
static constexpr int SLAB4 = (S + 1) * D4;              // 131104 float4 per (b,h)
static constexpr long long CACHE4 = (long long)B * H * S * D4;   // 2^25
static constexpr long long TENSOR4 = (long long)B * H * SLAB4;   // float4 per out tensor

static constexpr int TPB = 512;
static constexpr int UNROLL = 8;
static constexpr int BLOCKS_PER_TENSOR = (int)(CACHE4 / (TPB * UNROLL));  // 8192 exact
static constexpr int STATE_BLOCKS = (B * H * D4) / TPB; // 16

__global__ __launch_bounds__(TPB)
void kv_concat_fused_kernel(const float4* __restrict__ key_cache,
                            const float4* __restrict__ value_cache,
                            const float4* __restrict__ key_states,
                            const float4* __restrict__ value_states,
                            float4* __restrict__ out)
{
    const int t = blockIdx.y;                       // 0 = keys, 1 = values
    const float4* __restrict__ src = t ? value_cache : key_cache;
    float4* __restrict__ dst = out + (long long)t * TENSOR4;

    const long long j0 = (long long)blockIdx.x * (TPB * UNROLL) + threadIdx.x;

    // Front-batched loads (MLP = 8), streaming (evict-first) reads.
    float4 v[UNROLL];
#pragma unroll
    for (int u = 0; u < UNROLL; u++)
        v[u] = __ldcs(src + (j0 + (long long)u * TPB));

    // Streaming stores. out index = j + (bh<<5), bh = j>>17 (S*D4 = 2^17).
#pragma unroll
    for (int u = 0; u < UNROLL; u++) {
        long long j = j0 + (long long)u * TPB;
        __stcs(dst + (j + ((j >> 17) << 5)), v[u]);
    }

    // Fused state append: first STATE_BLOCKS blocks of each tensor write the
    // single new row per (b,h). One extra float4 per thread here (2 MB total).
    if (blockIdx.x < STATE_BLOCKS) {
        const int i = blockIdx.x * TPB + threadIdx.x;   // 0..8191
        const int bh   = i >> 5;                        // 0..255
        const int lane = i & 31;                        // 0..31
        const float4* __restrict__ states = t ? value_states : key_states;
        float4 sv = __ldcs(states + ((long long)bh * D4 + lane));
        dst[(long long)bh * SLAB4 + (long long)S * D4 + lane] = sv;
    }
}

extern "C" void kernel_launch(void* const* d_in, const int* in_sizes, int n_in,
                              void* d_out, int out_size)
{
    const float4* key_cache    = (const float4*)d_in[0];
    const float4* value_cache  = (const float4*)d_in[1];
    const float4* key_states   = (const float4*)d_in[2];
    const float4* value_states = (const float4*)d_in[3];
    float4* out = (float4*)d_out;

    dim3 grid(BLOCKS_PER_TENSOR, 2, 1);             // (8192, 2)
    kv_concat_fused_kernel<<<grid, TPB>>>(key_cache, value_cache,
                                          key_states, value_states, out);
}